// round 9
// baseline (speedup 1.0000x reference)
#include <cuda_runtime.h>
#include <mma.h>
#include <cstdint>
#include <cstddef>

using namespace nvcuda;

#define BB 4
#define PP 256
#define FIN 512
#define FOUT 512
#define NROWS (BB*PP)   // 1024

// ---------------- device scratch (no allocations allowed) -------------------
__device__ float g_H[NROWS * FOUT];          // fc output, tf32-rounded fp32 (2 MB)
__device__ float g_ss2[8][NROWS];            // per-nblock partial sum-of-squares
__device__ unsigned long long g_h1[NROWS];
__device__ unsigned long long g_h2[NROWS];
__device__ double g_loss;
__device__ unsigned int g_done = 0;          // K2 completion count (self-reset)

// ---------------- helpers ----------------------------------------------------
__device__ __forceinline__ void cp16(uint32_t saddr, const void* gptr) {
    asm volatile("cp.async.cg.shared.global [%0], [%1], 16;" :: "r"(saddr), "l"(gptr));
}
#define CP_COMMIT() asm volatile("cp.async.commit_group;" ::: "memory")
#define CP_WAIT(n)  asm volatile("cp.async.wait_group %0;" :: "n"(n) : "memory")

__device__ __forceinline__ void mma16n8k8(float c[4], const uint32_t a[4], const uint32_t b[2]) {
    asm volatile(
        "mma.sync.aligned.m16n8k8.row.col.f32.tf32.tf32.f32 "
        "{%0,%1,%2,%3}, {%4,%5,%6,%7}, {%8,%9}, {%0,%1,%2,%3};"
        : "+f"(c[0]), "+f"(c[1]), "+f"(c[2]), "+f"(c[3])
        : "r"(a[0]), "r"(a[1]), "r"(a[2]), "r"(a[3]), "r"(b[0]), "r"(b[1]));
}

__device__ __forceinline__ unsigned long long mix64(unsigned long long x) {
    x ^= x >> 30; x *= 0xbf58476d1ce4e5b9ULL;
    x ^= x >> 27; x *= 0x94d049bb133111ebULL;
    x ^= x >> 31;
    return x;
}

// ================= K1: hash + GEMM1 + norm partials ==========================
// g_H = round_tf32(inputs @ W^T + bias). 128 CTAs x 256 thr, 64x64 tiles.
// BK=64, 3-stage cp.async ring, 1 sync per chunk (8 chunks).
__global__ __launch_bounds__(256, 1)
void k1_gemm(const float* __restrict__ A, const float* __restrict__ labels,
             const float* __restrict__ W, const float* __restrict__ bias) {
    extern __shared__ float dyn[];            // As [3][64][68], Bs [3][64][68]
    const int cta = blockIdx.x;
    const int tid = threadIdx.x;
    const int wid = tid >> 5, lane = tid & 31;

    if (cta == 0 && tid == 0) g_loss = 0.0;

    // ---- hash: 128 CTAs x 8 warps = 1024 label rows
    {
        int gwarp = cta * 8 + wid;
        const float4* row = reinterpret_cast<const float4*>(labels + (size_t)gwarp * FIN);
        unsigned long long h1 = 0ull, h2 = 0ull;
#pragma unroll
        for (int i = 0; i < 4; i++) {
            float4 v = row[lane + 32 * i];
            int fb = (lane + 32 * i) * 4;
            float vv[4] = {v.x, v.y, v.z, v.w};
#pragma unroll
            for (int j = 0; j < 4; j++) {
                unsigned int bits = __float_as_uint(vv[j]);
                if (vv[j] == 0.0f) bits = 0u;
                unsigned long long x = (unsigned long long)bits
                    ^ ((unsigned long long)(fb + j + 1) * 0x9E3779B97F4A7C15ULL);
                h1 += mix64(x);
                h2 += mix64(x ^ 0xA5A5A5A5DEADBEEFULL);
            }
        }
#pragma unroll
        for (int o = 16; o > 0; o >>= 1) {
            h1 += __shfl_down_sync(0xffffffffu, h1, o);
            h2 += __shfl_down_sync(0xffffffffu, h2, o);
        }
        if (lane == 0) { g_h1[gwarp] = h1; g_h2[gwarp] = h2; }
    }

    // ---- GEMM
    const int nb = cta & 7;
    const int n0 = nb * 64;
    const int m0 = (cta >> 3) * 64;
    float* As = dyn;                          // [3][64][68]
    float* Bs = dyn + 3 * 64 * 68;
    uint32_t As_s = (uint32_t)__cvta_generic_to_shared(As);
    uint32_t Bs_s = (uint32_t)__cvta_generic_to_shared(Bs);

    const int wr = wid >> 1, wc = wid & 1;

    auto PREFETCH = [&](int s, int buf) {     // 64-wide k chunk
#pragma unroll
        for (int it = 0; it < 8; it++) {
            int idx = tid + it * 256;         // 0..2047
            int isA = idx < 1024;
            int j = isA ? idx : idx - 1024;
            int row = j >> 4, f = j & 15;
            const float* g = isA ? (A + (size_t)(m0 + row) * FIN + s * 64 + f * 4)
                                 : (W + (size_t)(n0 + row) * FIN + s * 64 + f * 4);
            uint32_t d = (isA ? As_s : Bs_s) + ((size_t)buf * 4352 + row * 68 + f * 4) * 4;
            cp16(d, g);
        }
        CP_COMMIT();
    };

    wmma::fragment<wmma::accumulator, 16, 16, 8, float> c0, c1;
    wmma::fill_fragment(c0, 0.0f);
    wmma::fill_fragment(c1, 0.0f);

    PREFETCH(0, 0);
    PREFETCH(1, 1);
#pragma unroll 1
    for (int s = 0; s < 8; s++) {
        const int buf = s % 3;
        if (s < 7) { CP_WAIT(1); } else { CP_WAIT(0); }
        __syncthreads();
        if (s + 2 < 8) PREFETCH(s + 2, (s + 2) % 3);
#pragma unroll
        for (int ks = 0; ks < 8; ks++) {
            wmma::fragment<wmma::matrix_a, 16, 16, 8, wmma::precision::tf32, wmma::row_major> a;
            wmma::fragment<wmma::matrix_b, 16, 16, 8, wmma::precision::tf32, wmma::col_major> b0, b1;
            wmma::load_matrix_sync(a,  As + (size_t)buf * 4352 + (wr * 16) * 68 + ks * 8, 68);
            wmma::load_matrix_sync(b0, Bs + (size_t)buf * 4352 + (wc * 32) * 68 + ks * 8, 68);
            wmma::load_matrix_sync(b1, Bs + (size_t)buf * 4352 + (wc * 32 + 16) * 68 + ks * 8, 68);
            wmma::mma_sync(c0, a, b0, c0);
            wmma::mma_sync(c1, a, b1, c1);
        }
    }
    __syncthreads();

    // ---- epilogue: stage, +bias, round to tf32, store, per-row SS partials
    float* stage = dyn;                       // [64][68]
    wmma::store_matrix_sync(stage + (size_t)(wr * 16) * 68 + wc * 32,      c0, 68, wmma::mem_row_major);
    wmma::store_matrix_sync(stage + (size_t)(wr * 16) * 68 + wc * 32 + 16, c1, 68, wmma::mem_row_major);
    __syncthreads();
#pragma unroll
    for (int t = 0; t < 4; t++) {
        int f4 = tid + t * 256;
        int row = f4 >> 4, c4 = (f4 & 15) * 4;
        float4 v = *reinterpret_cast<const float4*>(stage + (size_t)row * 68 + c4);
        float4 bv = *reinterpret_cast<const float4*>(bias + n0 + c4);
        v.x = wmma::__float_to_tf32(v.x + bv.x);
        v.y = wmma::__float_to_tf32(v.y + bv.y);
        v.z = wmma::__float_to_tf32(v.z + bv.z);
        v.w = wmma::__float_to_tf32(v.w + bv.w);
        *reinterpret_cast<float4*>(stage + (size_t)row * 68 + c4) = v;
        *reinterpret_cast<float4*>(g_H + (size_t)(m0 + row) * FOUT + n0 + c4) = v;
    }
    __syncthreads();
    {
        int row = tid >> 2;                   // 64 rows x 4 threads
        int cg = (tid & 3) * 16;
        float ss = 0.0f;
#pragma unroll
        for (int i = 0; i < 4; i++) {
            float4 v = *reinterpret_cast<const float4*>(stage + (size_t)row * 68 + cg + i * 4);
            ss += v.x * v.x + v.y * v.y + v.z * v.z + v.w * v.w;
        }
        ss += __shfl_xor_sync(0xffffffffu, ss, 1);
        ss += __shfl_xor_sync(0xffffffffu, ss, 2);
        if ((tid & 3) == 0) g_ss2[nb][m0 + row] = ss;
    }
}

// ================= K2: fused Gram + softmax + KL =============================
// 64 CTAs x 256 thr. CTA = (batch b, 16-row tile). A (16x512) loaded to smem
// once; B fragments loaded DIRECTLY from gmem (per-warp-private rows).
// Mainloop: 64 k8-steps, inline mma.m16n8k8.tf32, NO syncthreads.
__global__ __launch_bounds__(256, 1)
void k2_gram_kl(float* __restrict__ out) {
    extern __shared__ float dyn[];            // As [16][516] floats; later stage [16][260]
    __shared__ float inv_s[PP];
    __shared__ unsigned long long sh1[PP];
    __shared__ unsigned long long sh2[PP];
    __shared__ double wsum[8];

    const int cta = blockIdx.x;
    const int b = cta >> 4;
    const int m0 = (cta & 15) * 16;
    const int tid = threadIdx.x;
    const int wid = tid >> 5, lane = tid & 31;
    const int gq = lane >> 2;                 // groupID 0..7
    const int gm = lane & 3;                  // thread-in-group 0..3
    const float* Hb = g_H + (size_t)b * PP * FOUT;

    // ---- load A tile (16 x 512) into smem, stride 516 (bank-conflict-free)
    {
        uint32_t As_s = (uint32_t)__cvta_generic_to_shared(dyn);
#pragma unroll
        for (int it = 0; it < 8; it++) {
            int idx = tid + it * 256;         // 0..2047 f4
            int row = idx >> 7, f = idx & 127;
            cp16(As_s + ((size_t)row * 516 + f * 4) * 4,
                 Hb + (size_t)(m0 + row) * FOUT + f * 4);
        }
        CP_COMMIT();
    }

    // metadata (overlaps A load)
    {
        int q = tid;
        float ss = 0.0f;
#pragma unroll
        for (int nb = 0; nb < 8; nb++) ss += g_ss2[nb][b * PP + q];
        inv_s[q] = 1.0f / fmaxf(sqrtf(ss), 1e-12f);
        sh1[q] = g_h1[b * PP + q];
        sh2[q] = g_h2[b * PP + q];
    }
    CP_WAIT(0);
    __syncthreads();

    // ---- B row pointers: warp covers output cols wid*32..+31 = 4 n8 tiles
    const float* bp[4];
#pragma unroll
    for (int t = 0; t < 4; t++)
        bp[t] = Hb + (size_t)(wid * 32 + t * 8 + gq) * FOUT + gm;

    float acc[4][4];
#pragma unroll
    for (int t = 0; t < 4; t++)
#pragma unroll
        for (int i = 0; i < 4; i++) acc[t][i] = 0.0f;

    uint32_t areg[2][4], breg[2][4][2];
    auto loadA = [&](int s, int u) {
        const float* Ab = dyn;
        int col = 8 * s + gm;
        areg[u][0] = __float_as_uint(Ab[(size_t)gq * 516 + col]);
        areg[u][1] = __float_as_uint(Ab[(size_t)(gq + 8) * 516 + col]);
        areg[u][2] = __float_as_uint(Ab[(size_t)gq * 516 + col + 4]);
        areg[u][3] = __float_as_uint(Ab[(size_t)(gq + 8) * 516 + col + 4]);
    };
    auto loadB = [&](int s, int u) {
#pragma unroll
        for (int t = 0; t < 4; t++) {
            breg[u][t][0] = __float_as_uint(bp[t][8 * s]);
            breg[u][t][1] = __float_as_uint(bp[t][8 * s + 4]);
        }
    };

    loadA(0, 0);
    loadB(0, 0);
#pragma unroll 4
    for (int s = 0; s < 64; s++) {
        const int u = s & 1;
        if (s + 1 < 64) { loadA(s + 1, u ^ 1); loadB(s + 1, u ^ 1); }
#pragma unroll
        for (int t = 0; t < 4; t++) mma16n8k8(acc[t], areg[u], breg[u][t]);
    }
    __syncthreads();                          // A smem reads done -> reuse as stage

    // ---- stage S tile [16][260]
    float* stageS = dyn;
#pragma unroll
    for (int t = 0; t < 4; t++) {
        int cbase = wid * 32 + t * 8 + 2 * gm;
        stageS[(size_t)gq * 260 + cbase]           = acc[t][0];
        stageS[(size_t)gq * 260 + cbase + 1]       = acc[t][1];
        stageS[(size_t)(gq + 8) * 260 + cbase]     = acc[t][2];
        stageS[(size_t)(gq + 8) * 260 + cbase + 1] = acc[t][3];
    }
    __syncthreads();

    // ---- softmax + KL: 8 warps x 2 rows
    const float INV_TAU = 1.0f / 0.07f;
    double local = 0.0;
#pragma unroll
    for (int rr = 0; rr < 2; rr++) {
        const int pl = wid * 2 + rr;
        const float* Sr = stageS + (size_t)pl * 260;
        const float ip = inv_s[m0 + pl] * INV_TAU;
        float s[8];
        float mx = -1e30f;
#pragma unroll
        for (int j = 0; j < 8; j++) {
            int q = lane + 32 * j;
            s[j] = Sr[q] * ip * inv_s[q];
            mx = fmaxf(mx, s[j]);
        }
#pragma unroll
        for (int o = 16; o > 0; o >>= 1) mx = fmaxf(mx, __shfl_xor_sync(0xffffffffu, mx, o));
        float z = 0.0f;
#pragma unroll
        for (int j = 0; j < 8; j++) z += __expf(s[j] - mx);
#pragma unroll
        for (int o = 16; o > 0; o >>= 1) z += __shfl_xor_sync(0xffffffffu, z, o);
        float lse = mx + logf(z);

        unsigned long long h1p = sh1[m0 + pl], h2p = sh2[m0 + pl];
        int cnt = 0;
        bool match[8];
#pragma unroll
        for (int j = 0; j < 8; j++) {
            int q = lane + 32 * j;
            match[j] = (sh1[q] == h1p) && (sh2[q] == h2p);
            cnt += match[j] ? 1 : 0;
        }
#pragma unroll
        for (int o = 16; o > 0; o >>= 1) cnt += __shfl_xor_sync(0xffffffffu, cnt, o);

        float logn = logf((float)cnt);
        float contrib = 0.0f;
#pragma unroll
        for (int j = 0; j < 8; j++) {
            if (match[j]) {
                float lp = s[j] - lse;
                lp = fminf(fmaxf(lp, -11.512925464970229f),      // log(1e-5)
                           -1.0000050000290891e-05f);            // log(1-1e-5)
                contrib += (-logn - lp);
            }
        }
#pragma unroll
        for (int o = 16; o > 0; o >>= 1) contrib += __shfl_xor_sync(0xffffffffu, contrib, o);
        if (lane == 0) local += (double)contrib / (double)cnt;
    }
    if (lane == 0) wsum[wid] = local;
    __syncthreads();
    if (tid == 0) {
        double blk = 0.0;
#pragma unroll
        for (int i = 0; i < 8; i++) blk += wsum[i];
        atomicAdd(&g_loss, blk);
        __threadfence();
        if (atomicAdd(&g_done, 1u) == 63u) {     // last finisher writes output
            *(volatile unsigned int*)&g_done = 0;
            double l = atomicAdd(&g_loss, 0.0);
            out[0] = (float)(l * (1.0 / (double)(BB * PP)));
        }
    }
}

// ================= launch ====================================================
extern "C" void kernel_launch(void* const* d_in, const int* in_sizes, int n_in,
                              void* d_out, int out_size) {
    const float* inputs = (const float*)d_in[0];
    const float* labels = (const float*)d_in[1];
    const float* W      = (const float*)d_in[2];
    const float* bias   = (const float*)d_in[3];
    float* out = (float*)d_out;

    const int K1_SMEM = 2 * 3 * 64 * 68 * 4;     // 104448 B
    const int K2_SMEM = 16 * 516 * 4;            // 33024 B
    cudaFuncSetAttribute(k1_gemm,    cudaFuncAttributeMaxDynamicSharedMemorySize, K1_SMEM);
    cudaFuncSetAttribute(k2_gram_kl, cudaFuncAttributeMaxDynamicSharedMemorySize, K2_SMEM);

    k1_gemm<<<128, 256, K1_SMEM>>>(inputs, labels, W, bias);
    k2_gram_kl<<<64, 256, K2_SMEM>>>(out);
}

// round 10
// speedup vs baseline: 1.3463x; 1.3463x over previous
#include <cuda_runtime.h>
#include <mma.h>
#include <cuda_bf16.h>
#include <cstdint>
#include <cstddef>

using namespace nvcuda;

#define BB 4
#define PP 256
#define FIN 512
#define FOUT 512
#define NROWS (BB*PP)   // 1024

// ---------------- device scratch (no allocations allowed) -------------------
__device__ __nv_bfloat16 g_Hb[NROWS * FOUT]; // fc output, bf16-rounded (1 MB)
__device__ float g_ss2[8][NROWS];            // per-nblock partial sum-of-squares
__device__ unsigned long long g_h1[NROWS];
__device__ unsigned long long g_h2[NROWS];
__device__ double g_loss;
__device__ unsigned int g_done = 0;          // K2 completion count (self-reset)

__device__ __forceinline__ unsigned long long mix64(unsigned long long x) {
    x ^= x >> 30; x *= 0xbf58476d1ce4e5b9ULL;
    x ^= x >> 27; x *= 0x94d049bb133111ebULL;
    x ^= x >> 31;
    return x;
}

// ================= K1: hash + GEMM1 (tf32) + bf16 round + norm partials ======
// 128 CTAs x 256 thr, 64x64 tiles, BK=64, reg-staged LDG.128->STS.128 dbl-buf.
__global__ __launch_bounds__(256, 1)
void k1_gemm(const float* __restrict__ A, const float* __restrict__ labels,
             const float* __restrict__ W, const float* __restrict__ bias) {
    extern __shared__ float dyn[];            // As[2][64][68], Bs[2][64][68]
    const int cta = blockIdx.x;
    const int tid = threadIdx.x;
    const int wid = tid >> 5, lane = tid & 31;

    if (cta == 0 && tid == 0) g_loss = 0.0;

    // ---- hash: 128 CTAs x 8 warps = 1024 label rows
    {
        int gwarp = cta * 8 + wid;
        const float4* row = reinterpret_cast<const float4*>(labels + (size_t)gwarp * FIN);
        unsigned long long h1 = 0ull, h2 = 0ull;
#pragma unroll
        for (int i = 0; i < 4; i++) {
            float4 v = row[lane + 32 * i];
            int fb = (lane + 32 * i) * 4;
            float vv[4] = {v.x, v.y, v.z, v.w};
#pragma unroll
            for (int j = 0; j < 4; j++) {
                unsigned int bits = __float_as_uint(vv[j]);
                if (vv[j] == 0.0f) bits = 0u;
                unsigned long long x = (unsigned long long)bits
                    ^ ((unsigned long long)(fb + j + 1) * 0x9E3779B97F4A7C15ULL);
                h1 += mix64(x);
                h2 += mix64(x ^ 0xA5A5A5A5DEADBEEFULL);
            }
        }
#pragma unroll
        for (int o = 16; o > 0; o >>= 1) {
            h1 += __shfl_down_sync(0xffffffffu, h1, o);
            h2 += __shfl_down_sync(0xffffffffu, h2, o);
        }
        if (lane == 0) { g_h1[gwarp] = h1; g_h2[gwarp] = h2; }
    }

    // ---- GEMM: 64x64 output tile, BK=64, 8 chunks.
    const int nb = cta & 7;
    const int n0 = nb * 64;
    const int m0 = (cta >> 3) * 64;
    float* As = dyn;                          // [2][64][68]
    float* Bs = dyn + 2 * 64 * 68;            // [2][64][68]
    const int wr = wid >> 1, wc = wid & 1;
    const int lrow = tid >> 4;                // 0..15 (A/B row base, +16q)
    const int lf   = tid & 15;                // f4 within 64-wide chunk

    float4 pa[4], pb[4];
    auto LDG = [&](int s) {
#pragma unroll
        for (int q = 0; q < 4; q++) {
            int r = lrow + 16 * q;
            pa[q] = *reinterpret_cast<const float4*>(A + (size_t)(m0 + r) * FIN + s * 64 + lf * 4);
            pb[q] = *reinterpret_cast<const float4*>(W + (size_t)(n0 + r) * FIN + s * 64 + lf * 4);
        }
    };
    auto STS = [&](int buf) {
#pragma unroll
        for (int q = 0; q < 4; q++) {
            int r = lrow + 16 * q;
            *reinterpret_cast<float4*>(As + (size_t)buf * 4352 + r * 68 + lf * 4) = pa[q];
            *reinterpret_cast<float4*>(Bs + (size_t)buf * 4352 + r * 68 + lf * 4) = pb[q];
        }
    };

    wmma::fragment<wmma::accumulator, 16, 16, 8, float> c0, c1;
    wmma::fill_fragment(c0, 0.0f);
    wmma::fill_fragment(c1, 0.0f);

    LDG(0);
    STS(0);
    __syncthreads();

#pragma unroll 1
    for (int s = 0; s < 8; s++) {
        const int buf = s & 1;
        if (s + 1 < 8) LDG(s + 1);
#pragma unroll
        for (int ks = 0; ks < 8; ks++) {
            wmma::fragment<wmma::matrix_a, 16, 16, 8, wmma::precision::tf32, wmma::row_major> a;
            wmma::fragment<wmma::matrix_b, 16, 16, 8, wmma::precision::tf32, wmma::col_major> b0, b1;
            wmma::load_matrix_sync(a,  As + (size_t)buf * 4352 + (wr * 16) * 68 + ks * 8, 68);
            wmma::load_matrix_sync(b0, Bs + (size_t)buf * 4352 + (wc * 32) * 68 + ks * 8, 68);
            wmma::load_matrix_sync(b1, Bs + (size_t)buf * 4352 + (wc * 32 + 16) * 68 + ks * 8, 68);
            wmma::mma_sync(c0, a, b0, c0);
            wmma::mma_sync(c1, a, b1, c1);
        }
        if (s + 1 < 8) STS(buf ^ 1);
        __syncthreads();
    }

    // ---- epilogue: stage fp32, +bias, round bf16, store g_Hb, SS partials
    float* stage = dyn;                       // [64][68]
    wmma::store_matrix_sync(stage + (size_t)(wr * 16) * 68 + wc * 32,      c0, 68, wmma::mem_row_major);
    wmma::store_matrix_sync(stage + (size_t)(wr * 16) * 68 + wc * 32 + 16, c1, 68, wmma::mem_row_major);
    __syncthreads();
    float ssl[4];                             // per-thread SS of its 4 rounded vals
#pragma unroll
    for (int t = 0; t < 4; t++) {
        int f4 = tid + t * 256;
        int row = f4 >> 4, c4 = (f4 & 15) * 4;
        float4 v = *reinterpret_cast<const float4*>(stage + (size_t)row * 68 + c4);
        float4 bv = *reinterpret_cast<const float4*>(bias + n0 + c4);
        __nv_bfloat162 lo = __float22bfloat162_rn(make_float2(v.x + bv.x, v.y + bv.y));
        __nv_bfloat162 hi = __float22bfloat162_rn(make_float2(v.z + bv.z, v.w + bv.w));
        *reinterpret_cast<__nv_bfloat162*>(g_Hb + (size_t)(m0 + row) * FOUT + n0 + c4)     = lo;
        *reinterpret_cast<__nv_bfloat162*>(g_Hb + (size_t)(m0 + row) * FOUT + n0 + c4 + 2) = hi;
        float lx = __bfloat162float(lo.x), ly = __bfloat162float(lo.y);
        float hx = __bfloat162float(hi.x), hy = __bfloat162float(hi.y);
        ssl[t] = lx * lx + ly * ly + hx * hx + hy * hy;
        // also write rounded values back to stage for the SS reduction
        *reinterpret_cast<float4*>(stage + (size_t)row * 68 + c4) = make_float4(lx, ly, hx, hy);
    }
    __syncthreads();
    {
        int row = tid >> 2;                   // 64 rows x 4 threads x 16 cols
        int cg = (tid & 3) * 16;
        float ss = 0.0f;
#pragma unroll
        for (int i = 0; i < 4; i++) {
            float4 v = *reinterpret_cast<const float4*>(stage + (size_t)row * 68 + cg + i * 4);
            ss += v.x * v.x + v.y * v.y + v.z * v.z + v.w * v.w;
        }
        ss += __shfl_xor_sync(0xffffffffu, ss, 1);
        ss += __shfl_xor_sync(0xffffffffu, ss, 2);
        if ((tid & 3) == 0) g_ss2[nb][m0 + row] = ss;
        (void)ssl;
    }
}

// ================= K2: fused Gram (bf16) + softmax + KL ======================
// 64 CTAs x 256 thr. CTA = (batch b, 16-row tile). A tile (16x512 bf16) in
// smem once; B streamed in k=64 chunks [256][80] bf16, reg-staged dbl-buffer.
__global__ __launch_bounds__(256, 1)
void k2_gram_kl(float* __restrict__ out) {
    extern __shared__ float dynf[];
    __nv_bfloat16* Asm = reinterpret_cast<__nv_bfloat16*>(dynf);          // [16][528]
    __nv_bfloat16* Bsm = reinterpret_cast<__nv_bfloat16*>(dynf) + 16*528; // [2][256][80]
    __shared__ float inv_s[PP];
    __shared__ unsigned long long sh1[PP];
    __shared__ unsigned long long sh2[PP];
    __shared__ double wsum[8];

    const int cta = blockIdx.x;
    const int b = cta >> 4;
    const int m0 = (cta & 15) * 16;
    const int tid = threadIdx.x;
    const int wid = tid >> 5, lane = tid & 31;
    const __nv_bfloat16* Hb = g_Hb + (size_t)b * PP * FOUT;

    // ---- A tile: 16 x 512 bf16 = 1024 x 16B. 4 f4 per thread.
    float4 pa4[4];
#pragma unroll
    for (int q = 0; q < 4; q++) {
        int idx = tid + q * 256;
        int row = idx >> 6, f = idx & 63;     // f: 16B unit within row
        pa4[q] = *reinterpret_cast<const float4*>(
            reinterpret_cast<const char*>(Hb + (size_t)(m0 + row) * FOUT) + f * 16);
    }
    // ---- B chunk staging: 256 rows x 64 bf16 = 2048 x 16B. 8 f4 per thread.
    const int brow = tid >> 1;                // rows brow + 128q? -> use idx scheme
    float4 pb4[8];
    auto LDG_B = [&](int s) {
#pragma unroll
        for (int q = 0; q < 8; q++) {
            int idx = tid + q * 256;
            int row = idx >> 3, f = idx & 7;
            pb4[q] = *reinterpret_cast<const float4*>(
                reinterpret_cast<const char*>(Hb + (size_t)row * FOUT) + s * 128 + f * 16);
        }
    };
    auto STS_B = [&](int buf) {
#pragma unroll
        for (int q = 0; q < 8; q++) {
            int idx = tid + q * 256;
            int row = idx >> 3, f = idx & 7;
            *reinterpret_cast<float4*>(
                reinterpret_cast<char*>(Bsm + (size_t)buf * 256 * 80 + row * 80) + f * 16) = pb4[q];
        }
    };

    LDG_B(0);
    // store A (dst rows stride 528 bf16 = 1056 B, 16B multiple)
#pragma unroll
    for (int q = 0; q < 4; q++) {
        int idx = tid + q * 256;
        int row = idx >> 6, f = idx & 63;
        *reinterpret_cast<float4*>(reinterpret_cast<char*>(Asm + (size_t)row * 528) + f * 16) = pa4[q];
    }
    // metadata
    {
        int q = tid;
        float ss = 0.0f;
#pragma unroll
        for (int nb = 0; nb < 8; nb++) ss += g_ss2[nb][b * PP + q];
        inv_s[q] = 1.0f / fmaxf(sqrtf(ss), 1e-12f);
        sh1[q] = g_h1[b * PP + q];
        sh2[q] = g_h2[b * PP + q];
    }
    STS_B(0);
    __syncthreads();

    wmma::fragment<wmma::accumulator, 16, 16, 16, float> c0, c1;
    wmma::fill_fragment(c0, 0.0f);
    wmma::fill_fragment(c1, 0.0f);

#pragma unroll 1
    for (int s = 0; s < 8; s++) {
        const int buf = s & 1;
        if (s + 1 < 8) LDG_B(s + 1);
#pragma unroll
        for (int ks = 0; ks < 4; ks++) {      // 64 / 16
            wmma::fragment<wmma::matrix_a, 16, 16, 16, __nv_bfloat16, wmma::row_major> a;
            wmma::fragment<wmma::matrix_b, 16, 16, 16, __nv_bfloat16, wmma::col_major> b0, b1;
            wmma::load_matrix_sync(a, Asm + s * 64 + ks * 16, 528);
            const __nv_bfloat16* bb = Bsm + (size_t)buf * 256 * 80 + ks * 16;
            wmma::load_matrix_sync(b0, bb + (size_t)(wid * 32) * 80, 80);
            wmma::load_matrix_sync(b1, bb + (size_t)(wid * 32 + 16) * 80, 80);
            wmma::mma_sync(c0, a, b0, c0);
            wmma::mma_sync(c1, a, b1, c1);
        }
        if (s + 1 < 8) STS_B(buf ^ 1);
        __syncthreads();
    }

    // ---- stage S tile [16][260] fp32 over dyn
    float* stageS = dynf;
    wmma::store_matrix_sync(stageS + wid * 32,      c0, 260, wmma::mem_row_major);
    wmma::store_matrix_sync(stageS + wid * 32 + 16, c1, 260, wmma::mem_row_major);
    __syncthreads();

    // ---- softmax + KL: 8 warps x 2 rows
    const float INV_TAU = 1.0f / 0.07f;
    double local = 0.0;
#pragma unroll
    for (int rr = 0; rr < 2; rr++) {
        const int pl = wid * 2 + rr;
        const float* Sr = stageS + (size_t)pl * 260;
        const float ip = inv_s[m0 + pl] * INV_TAU;
        float s[8];
        float mx = -1e30f;
#pragma unroll
        for (int j = 0; j < 8; j++) {
            int q = lane + 32 * j;
            s[j] = Sr[q] * ip * inv_s[q];
            mx = fmaxf(mx, s[j]);
        }
#pragma unroll
        for (int o = 16; o > 0; o >>= 1) mx = fmaxf(mx, __shfl_xor_sync(0xffffffffu, mx, o));
        float z = 0.0f;
#pragma unroll
        for (int j = 0; j < 8; j++) z += __expf(s[j] - mx);
#pragma unroll
        for (int o = 16; o > 0; o >>= 1) z += __shfl_xor_sync(0xffffffffu, z, o);
        float lse = mx + logf(z);

        unsigned long long h1p = sh1[m0 + pl], h2p = sh2[m0 + pl];
        int cnt = 0;
        bool match[8];
#pragma unroll
        for (int j = 0; j < 8; j++) {
            int q = lane + 32 * j;
            match[j] = (sh1[q] == h1p) && (sh2[q] == h2p);
            cnt += match[j] ? 1 : 0;
        }
#pragma unroll
        for (int o = 16; o > 0; o >>= 1) cnt += __shfl_xor_sync(0xffffffffu, cnt, o);

        float logn = logf((float)cnt);
        float contrib = 0.0f;
#pragma unroll
        for (int j = 0; j < 8; j++) {
            if (match[j]) {
                float lp = s[j] - lse;
                lp = fminf(fmaxf(lp, -11.512925464970229f),      // log(1e-5)
                           -1.0000050000290891e-05f);            // log(1-1e-5)
                contrib += (-logn - lp);
            }
        }
#pragma unroll
        for (int o = 16; o > 0; o >>= 1) contrib += __shfl_xor_sync(0xffffffffu, contrib, o);
        if (lane == 0) local += (double)contrib / (double)cnt;
    }
    if (lane == 0) wsum[wid] = local;
    __syncthreads();
    if (tid == 0) {
        double blk = 0.0;
#pragma unroll
        for (int i = 0; i < 8; i++) blk += wsum[i];
        atomicAdd(&g_loss, blk);
        __threadfence();
        if (atomicAdd(&g_done, 1u) == 63u) {     // last finisher writes output
            *(volatile unsigned int*)&g_done = 0;
            double l = atomicAdd(&g_loss, 0.0);
            out[0] = (float)(l * (1.0 / (double)(BB * PP)));
        }
    }
    (void)brow;
}

// ================= launch ====================================================
extern "C" void kernel_launch(void* const* d_in, const int* in_sizes, int n_in,
                              void* d_out, int out_size) {
    const float* inputs = (const float*)d_in[0];
    const float* labels = (const float*)d_in[1];
    const float* W      = (const float*)d_in[2];
    const float* bias   = (const float*)d_in[3];
    float* out = (float*)d_out;

    const int K1_SMEM = 2 * 2 * 64 * 68 * 4;                  // 69632 B
    const int K2_SMEM = (16 * 528 + 2 * 256 * 80) * 2;        // 98816 B
    cudaFuncSetAttribute(k1_gemm,    cudaFuncAttributeMaxDynamicSharedMemorySize, K1_SMEM);
    cudaFuncSetAttribute(k2_gram_kl, cudaFuncAttributeMaxDynamicSharedMemorySize, K2_SMEM);

    k1_gemm<<<128, 256, K1_SMEM>>>(inputs, labels, W, bias);
    k2_gram_kl<<<64, 256, K2_SMEM>>>(out);
}

// round 11
// speedup vs baseline: 1.6624x; 1.2348x over previous
#include <cuda_runtime.h>
#include <mma.h>
#include <cuda_bf16.h>
#include <cstdint>
#include <cstddef>

using namespace nvcuda;

#define BB 4
#define PP 256
#define FIN 512
#define FOUT 512
#define NROWS (BB*PP)   // 1024

// ---------------- device scratch (no allocations allowed) -------------------
__device__ __nv_bfloat16 g_Hb[NROWS * FOUT]; // fc output, bf16-rounded (1 MB)
__device__ float g_ss2[8][NROWS];            // per-nblock partial sum-of-squares
__device__ unsigned long long g_h1[NROWS];
__device__ unsigned long long g_h2[NROWS];
__device__ double g_loss;
__device__ unsigned int g_done = 0;          // K2 completion count (self-reset)

__device__ __forceinline__ unsigned long long mix64(unsigned long long x) {
    x ^= x >> 30; x *= 0xbf58476d1ce4e5b9ULL;
    x ^= x >> 27; x *= 0x94d049bb133111ebULL;
    x ^= x >> 31;
    return x;
}

// ================= K1: hash + bf16 GEMM1 + bf16 round + norm partials ========
// 128 CTAs x 256 thr, 64x64 tiles, BK=64 (8 chunks), reg-staged dbl-buffer.
// smem bf16 tiles stride 72 (144B rows -> conflict-free LDSM).
__global__ __launch_bounds__(256, 1)
void k1_gemm(const float* __restrict__ A, const float* __restrict__ labels,
             const float* __restrict__ W, const float* __restrict__ bias) {
    extern __shared__ __align__(16) __nv_bfloat16 dynb[];   // As[2][64][72], Bs[2][64][72]
    const int cta = blockIdx.x;
    const int tid = threadIdx.x;
    const int wid = tid >> 5, lane = tid & 31;

    if (cta == 0 && tid == 0) g_loss = 0.0;

    // ---- hash: 128 CTAs x 8 warps = 1024 label rows
    {
        int gwarp = cta * 8 + wid;
        const float4* row = reinterpret_cast<const float4*>(labels + (size_t)gwarp * FIN);
        unsigned long long h1 = 0ull, h2 = 0ull;
#pragma unroll
        for (int i = 0; i < 4; i++) {
            float4 v = row[lane + 32 * i];
            int fb = (lane + 32 * i) * 4;
            float vv[4] = {v.x, v.y, v.z, v.w};
#pragma unroll
            for (int j = 0; j < 4; j++) {
                unsigned int bits = __float_as_uint(vv[j]);
                if (vv[j] == 0.0f) bits = 0u;
                unsigned long long x = (unsigned long long)bits
                    ^ ((unsigned long long)(fb + j + 1) * 0x9E3779B97F4A7C15ULL);
                h1 += mix64(x);
                h2 += mix64(x ^ 0xA5A5A5A5DEADBEEFULL);
            }
        }
#pragma unroll
        for (int o = 16; o > 0; o >>= 1) {
            h1 += __shfl_down_sync(0xffffffffu, h1, o);
            h2 += __shfl_down_sync(0xffffffffu, h2, o);
        }
        if (lane == 0) { g_h1[gwarp] = h1; g_h2[gwarp] = h2; }
    }

    // ---- GEMM: 64x64 tile, BK=64.
    const int nb = cta & 7;
    const int n0 = nb * 64;
    const int m0 = (cta >> 3) * 64;
    __nv_bfloat16* Asm = dynb;                // [2][64][72]
    __nv_bfloat16* Bsm = dynb + 2 * 64 * 72;  // [2][64][72]
    const int wr = wid >> 1, wc = wid & 1;

    float4 pa[4], pb[4];
    auto LDG = [&](int s) {
#pragma unroll
        for (int q = 0; q < 4; q++) {
            int idx = tid + q * 256;          // 0..1023
            int row = idx >> 4, f = idx & 15;
            pa[q] = *reinterpret_cast<const float4*>(A + (size_t)(m0 + row) * FIN + s * 64 + f * 4);
            pb[q] = *reinterpret_cast<const float4*>(W + (size_t)(n0 + row) * FIN + s * 64 + f * 4);
        }
    };
    auto STS = [&](int buf) {
#pragma unroll
        for (int q = 0; q < 4; q++) {
            int idx = tid + q * 256;
            int row = idx >> 4, f = idx & 15;
            __nv_bfloat162 a0 = __float22bfloat162_rn(make_float2(pa[q].x, pa[q].y));
            __nv_bfloat162 a1 = __float22bfloat162_rn(make_float2(pa[q].z, pa[q].w));
            __nv_bfloat162 b0 = __float22bfloat162_rn(make_float2(pb[q].x, pb[q].y));
            __nv_bfloat162 b1 = __float22bfloat162_rn(make_float2(pb[q].z, pb[q].w));
            uint2 va, vb;
            va.x = reinterpret_cast<uint32_t&>(a0); va.y = reinterpret_cast<uint32_t&>(a1);
            vb.x = reinterpret_cast<uint32_t&>(b0); vb.y = reinterpret_cast<uint32_t&>(b1);
            *reinterpret_cast<uint2*>(Asm + (size_t)buf * 4608 + row * 72 + f * 4) = va;
            *reinterpret_cast<uint2*>(Bsm + (size_t)buf * 4608 + row * 72 + f * 4) = vb;
        }
    };

    wmma::fragment<wmma::accumulator, 16, 16, 16, float> c0, c1;
    wmma::fill_fragment(c0, 0.0f);
    wmma::fill_fragment(c1, 0.0f);

    LDG(0);
    STS(0);
    __syncthreads();

#pragma unroll 1
    for (int s = 0; s < 8; s++) {
        const int buf = s & 1;
        if (s + 1 < 8) LDG(s + 1);
#pragma unroll
        for (int ks = 0; ks < 4; ks++) {
            wmma::fragment<wmma::matrix_a, 16, 16, 16, __nv_bfloat16, wmma::row_major> a;
            wmma::fragment<wmma::matrix_b, 16, 16, 16, __nv_bfloat16, wmma::col_major> b0, b1;
            wmma::load_matrix_sync(a,  Asm + (size_t)buf * 4608 + (wr * 16) * 72 + ks * 16, 72);
            wmma::load_matrix_sync(b0, Bsm + (size_t)buf * 4608 + (wc * 32) * 72 + ks * 16, 72);
            wmma::load_matrix_sync(b1, Bsm + (size_t)buf * 4608 + (wc * 32 + 16) * 72 + ks * 16, 72);
            wmma::mma_sync(c0, a, b0, c0);
            wmma::mma_sync(c1, a, b1, c1);
        }
        if (s + 1 < 8) STS(buf ^ 1);
        __syncthreads();
    }

    // ---- epilogue: stage fp32, +bias, round bf16, store g_Hb, SS partials
    float* stage = reinterpret_cast<float*>(dynb);   // [64][68] = 17408 B
    wmma::store_matrix_sync(stage + (size_t)(wr * 16) * 68 + wc * 32,      c0, 68, wmma::mem_row_major);
    wmma::store_matrix_sync(stage + (size_t)(wr * 16) * 68 + wc * 32 + 16, c1, 68, wmma::mem_row_major);
    __syncthreads();
#pragma unroll
    for (int t = 0; t < 4; t++) {
        int f4 = tid + t * 256;
        int row = f4 >> 4, c4 = (f4 & 15) * 4;
        float4 v = *reinterpret_cast<const float4*>(stage + (size_t)row * 68 + c4);
        float4 bv = *reinterpret_cast<const float4*>(bias + n0 + c4);
        __nv_bfloat162 lo = __float22bfloat162_rn(make_float2(v.x + bv.x, v.y + bv.y));
        __nv_bfloat162 hi = __float22bfloat162_rn(make_float2(v.z + bv.z, v.w + bv.w));
        *reinterpret_cast<__nv_bfloat162*>(g_Hb + (size_t)(m0 + row) * FOUT + n0 + c4)     = lo;
        *reinterpret_cast<__nv_bfloat162*>(g_Hb + (size_t)(m0 + row) * FOUT + n0 + c4 + 2) = hi;
        float lx = __bfloat162float(lo.x), ly = __bfloat162float(lo.y);
        float hx = __bfloat162float(hi.x), hy = __bfloat162float(hi.y);
        *reinterpret_cast<float4*>(stage + (size_t)row * 68 + c4) = make_float4(lx, ly, hx, hy);
    }
    __syncthreads();
    {
        int row = tid >> 2;                   // 64 rows x 4 threads x 16 cols
        int cg = (tid & 3) * 16;
        float ss = 0.0f;
#pragma unroll
        for (int i = 0; i < 4; i++) {
            float4 v = *reinterpret_cast<const float4*>(stage + (size_t)row * 68 + cg + i * 4);
            ss += v.x * v.x + v.y * v.y + v.z * v.z + v.w * v.w;
        }
        ss += __shfl_xor_sync(0xffffffffu, ss, 1);
        ss += __shfl_xor_sync(0xffffffffu, ss, 2);
        if ((tid & 3) == 0) g_ss2[nb][m0 + row] = ss;
    }
}

// ================= K2: fused Gram (bf16) + softmax + KL ======================
// 64 CTAs x 256 thr. CTA = (batch b, 16-row tile). A (16x512 bf16) resident in
// smem (stride 520 -> conflict-free); B streamed k=64 chunks [256][72] bf16.
__global__ __launch_bounds__(256, 1)
void k2_gram_kl(float* __restrict__ out) {
    extern __shared__ __align__(16) float dynf[];
    __nv_bfloat16* Asm = reinterpret_cast<__nv_bfloat16*>(dynf);            // [16][520]
    __nv_bfloat16* Bsm = reinterpret_cast<__nv_bfloat16*>(dynf) + 16 * 520; // [2][256][72]
    __shared__ float inv_s[PP];
    __shared__ unsigned long long sh1[PP];
    __shared__ unsigned long long sh2[PP];
    __shared__ double wsum[8];

    const int cta = blockIdx.x;
    const int b = cta >> 4;
    const int m0 = (cta & 15) * 16;
    const int tid = threadIdx.x;
    const int wid = tid >> 5, lane = tid & 31;
    const __nv_bfloat16* Hb = g_Hb + (size_t)b * PP * FOUT;

    // ---- A tile: 16 x 512 bf16 = 1024 x 16B, 4 per thread
    float4 pa4[4];
#pragma unroll
    for (int q = 0; q < 4; q++) {
        int idx = tid + q * 256;
        int row = idx >> 6, f = idx & 63;
        pa4[q] = *reinterpret_cast<const float4*>(
            reinterpret_cast<const char*>(Hb + (size_t)(m0 + row) * FOUT) + f * 16);
    }
    // ---- B chunk staging: 256 rows x 64 bf16 = 2048 x 16B, 8 per thread
    float4 pb4[8];
    auto LDG_B = [&](int s) {
#pragma unroll
        for (int q = 0; q < 8; q++) {
            int idx = tid + q * 256;
            int row = idx >> 3, f = idx & 7;
            pb4[q] = *reinterpret_cast<const float4*>(
                reinterpret_cast<const char*>(Hb + (size_t)row * FOUT) + s * 128 + f * 16);
        }
    };
    auto STS_B = [&](int buf) {
#pragma unroll
        for (int q = 0; q < 8; q++) {
            int idx = tid + q * 256;
            int row = idx >> 3, f = idx & 7;
            *reinterpret_cast<float4*>(
                reinterpret_cast<char*>(Bsm + (size_t)buf * 256 * 72) + row * 144 + f * 16) = pb4[q];
        }
    };

    LDG_B(0);
#pragma unroll
    for (int q = 0; q < 4; q++) {
        int idx = tid + q * 256;
        int row = idx >> 6, f = idx & 63;
        *reinterpret_cast<float4*>(reinterpret_cast<char*>(Asm) + row * 1040 + f * 16) = pa4[q];
    }
    // metadata (overlaps loads)
    {
        int q = tid;
        float ss = 0.0f;
#pragma unroll
        for (int nb = 0; nb < 8; nb++) ss += g_ss2[nb][b * PP + q];
        inv_s[q] = 1.0f / fmaxf(sqrtf(ss), 1e-12f);
        sh1[q] = g_h1[b * PP + q];
        sh2[q] = g_h2[b * PP + q];
    }
    STS_B(0);
    __syncthreads();

    wmma::fragment<wmma::accumulator, 16, 16, 16, float> c0, c1;
    wmma::fill_fragment(c0, 0.0f);
    wmma::fill_fragment(c1, 0.0f);

#pragma unroll 1
    for (int s = 0; s < 8; s++) {
        const int buf = s & 1;
        if (s + 1 < 8) LDG_B(s + 1);
#pragma unroll
        for (int ks = 0; ks < 4; ks++) {
            wmma::fragment<wmma::matrix_a, 16, 16, 16, __nv_bfloat16, wmma::row_major> a;
            wmma::fragment<wmma::matrix_b, 16, 16, 16, __nv_bfloat16, wmma::col_major> b0, b1;
            wmma::load_matrix_sync(a, Asm + s * 64 + ks * 16, 520);
            const __nv_bfloat16* bb = Bsm + (size_t)buf * 256 * 72 + ks * 16;
            wmma::load_matrix_sync(b0, bb + (size_t)(wid * 32) * 72, 72);
            wmma::load_matrix_sync(b1, bb + (size_t)(wid * 32 + 16) * 72, 72);
            wmma::mma_sync(c0, a, b0, c0);
            wmma::mma_sync(c1, a, b1, c1);
        }
        if (s + 1 < 8) STS_B(buf ^ 1);
        __syncthreads();
    }

    // ---- stage S tile [16][260] fp32
    float* stageS = dynf;
    wmma::store_matrix_sync(stageS + wid * 32,      c0, 260, wmma::mem_row_major);
    wmma::store_matrix_sync(stageS + wid * 32 + 16, c1, 260, wmma::mem_row_major);
    __syncthreads();

    // ---- softmax + KL: 8 warps x 2 rows
    const float INV_TAU = 1.0f / 0.07f;
    double local = 0.0;
#pragma unroll
    for (int rr = 0; rr < 2; rr++) {
        const int pl = wid * 2 + rr;
        const float* Sr = stageS + (size_t)pl * 260;
        const float ip = inv_s[m0 + pl] * INV_TAU;
        float s[8];
        float mx = -1e30f;
#pragma unroll
        for (int j = 0; j < 8; j++) {
            int q = lane + 32 * j;
            s[j] = Sr[q] * ip * inv_s[q];
            mx = fmaxf(mx, s[j]);
        }
#pragma unroll
        for (int o = 16; o > 0; o >>= 1) mx = fmaxf(mx, __shfl_xor_sync(0xffffffffu, mx, o));
        float z = 0.0f;
#pragma unroll
        for (int j = 0; j < 8; j++) z += __expf(s[j] - mx);
#pragma unroll
        for (int o = 16; o > 0; o >>= 1) z += __shfl_xor_sync(0xffffffffu, z, o);
        float lse = mx + logf(z);

        unsigned long long h1p = sh1[m0 + pl], h2p = sh2[m0 + pl];
        int cnt = 0;
        bool match[8];
#pragma unroll
        for (int j = 0; j < 8; j++) {
            int q = lane + 32 * j;
            match[j] = (sh1[q] == h1p) && (sh2[q] == h2p);
            cnt += match[j] ? 1 : 0;
        }
#pragma unroll
        for (int o = 16; o > 0; o >>= 1) cnt += __shfl_xor_sync(0xffffffffu, cnt, o);

        float logn = logf((float)cnt);
        float contrib = 0.0f;
#pragma unroll
        for (int j = 0; j < 8; j++) {
            if (match[j]) {
                float lp = s[j] - lse;
                lp = fminf(fmaxf(lp, -11.512925464970229f),      // log(1e-5)
                           -1.0000050000290891e-05f);            // log(1-1e-5)
                contrib += (-logn - lp);
            }
        }
#pragma unroll
        for (int o = 16; o > 0; o >>= 1) contrib += __shfl_xor_sync(0xffffffffu, contrib, o);
        if (lane == 0) local += (double)contrib / (double)cnt;
    }
    if (lane == 0) wsum[wid] = local;
    __syncthreads();
    if (tid == 0) {
        double blk = 0.0;
#pragma unroll
        for (int i = 0; i < 8; i++) blk += wsum[i];
        atomicAdd(&g_loss, blk);
        __threadfence();
        if (atomicAdd(&g_done, 1u) == 63u) {     // last finisher writes output
            *(volatile unsigned int*)&g_done = 0;
            double l = atomicAdd(&g_loss, 0.0);
            out[0] = (float)(l * (1.0 / (double)(BB * PP)));
        }
    }
}

// ================= launch ====================================================
extern "C" void kernel_launch(void* const* d_in, const int* in_sizes, int n_in,
                              void* d_out, int out_size) {
    const float* inputs = (const float*)d_in[0];
    const float* labels = (const float*)d_in[1];
    const float* W      = (const float*)d_in[2];
    const float* bias   = (const float*)d_in[3];
    float* out = (float*)d_out;

    const int K1_SMEM = 2 * 2 * 64 * 72 * 2;                 // 36864 B
    const int K2_SMEM = (16 * 520 + 2 * 256 * 72) * 2;       // 90368 B
    cudaFuncSetAttribute(k1_gemm,    cudaFuncAttributeMaxDynamicSharedMemorySize, K1_SMEM);
    cudaFuncSetAttribute(k2_gram_kl, cudaFuncAttributeMaxDynamicSharedMemorySize, K2_SMEM);

    k1_gemm<<<128, 256, K1_SMEM>>>(inputs, labels, W, bias);
    k2_gram_kl<<<64, 256, K2_SMEM>>>(out);
}

// round 12
// speedup vs baseline: 1.6880x; 1.0154x over previous
#include <cuda_runtime.h>
#include <mma.h>
#include <cuda_bf16.h>
#include <cstdint>
#include <cstddef>

using namespace nvcuda;

#define BB 4
#define PP 256
#define FIN 512
#define FOUT 512
#define NROWS (BB*PP)   // 1024

// ---------------- device scratch (no allocations allowed) -------------------
__device__ __nv_bfloat16 g_Hb[NROWS * FOUT]; // fc output, bf16-rounded (1 MB)
__device__ float g_ss2[8][NROWS];            // per-nblock partial sum-of-squares
__device__ unsigned long long g_h1[NROWS];
__device__ unsigned long long g_h2[NROWS];
__device__ double g_loss;
__device__ unsigned int g_done = 0;          // K2 completion count (self-reset)

__device__ __forceinline__ unsigned long long mix64(unsigned long long x) {
    x ^= x >> 30; x *= 0xbf58476d1ce4e5b9ULL;
    x ^= x >> 27; x *= 0x94d049bb133111ebULL;
    x ^= x >> 31;
    return x;
}

// ================= K1: hash + bf16 GEMM1 + bf16 round + norm partials ========
// 128 CTAs x 512 thr (16 warps, 4x4 grid, warp tile 16x16), 64x64 tiles,
// BK=64 (8 chunks), reg-staged dbl-buffer, stride-72 bf16 smem (conflict-free).
__global__ __launch_bounds__(512, 1)
void k1_gemm(const float* __restrict__ A, const float* __restrict__ labels,
             const float* __restrict__ W, const float* __restrict__ bias) {
    extern __shared__ __align__(16) __nv_bfloat16 dynb[];   // As[2][64][72], Bs[2][64][72]
    const int cta = blockIdx.x;
    const int tid = threadIdx.x;
    const int wid = tid >> 5, lane = tid & 31;

    if (cta == 0 && tid == 0) g_loss = 0.0;

    // ---- hash: warps 0..7 only -> 128 CTAs x 8 = 1024 label rows
    if (wid < 8) {
        int gwarp = cta * 8 + wid;
        const float4* row = reinterpret_cast<const float4*>(labels + (size_t)gwarp * FIN);
        unsigned long long h1 = 0ull, h2 = 0ull;
#pragma unroll
        for (int i = 0; i < 4; i++) {
            float4 v = row[lane + 32 * i];
            int fb = (lane + 32 * i) * 4;
            float vv[4] = {v.x, v.y, v.z, v.w};
#pragma unroll
            for (int j = 0; j < 4; j++) {
                unsigned int bits = __float_as_uint(vv[j]);
                if (vv[j] == 0.0f) bits = 0u;
                unsigned long long x = (unsigned long long)bits
                    ^ ((unsigned long long)(fb + j + 1) * 0x9E3779B97F4A7C15ULL);
                h1 += mix64(x);
                h2 += mix64(x ^ 0xA5A5A5A5DEADBEEFULL);
            }
        }
#pragma unroll
        for (int o = 16; o > 0; o >>= 1) {
            h1 += __shfl_down_sync(0xffffffffu, h1, o);
            h2 += __shfl_down_sync(0xffffffffu, h2, o);
        }
        if (lane == 0) { g_h1[gwarp] = h1; g_h2[gwarp] = h2; }
    }

    // ---- GEMM: 64x64 tile, BK=64, 8 chunks
    const int nb = cta & 7;
    const int n0 = nb * 64;
    const int m0 = (cta >> 3) * 64;
    __nv_bfloat16* Asm = dynb;                // [2][64][72]
    __nv_bfloat16* Bsm = dynb + 2 * 64 * 72;  // [2][64][72]
    const int wr = wid >> 2, wc = wid & 3;    // 4x4 warp grid

    float4 pa[2], pb[2];
    auto LDG = [&](int s) {
#pragma unroll
        for (int q = 0; q < 2; q++) {
            int idx = tid + q * 512;          // 0..1023
            int row = idx >> 4, f = idx & 15;
            pa[q] = *reinterpret_cast<const float4*>(A + (size_t)(m0 + row) * FIN + s * 64 + f * 4);
            pb[q] = *reinterpret_cast<const float4*>(W + (size_t)(n0 + row) * FIN + s * 64 + f * 4);
        }
    };
    auto STS = [&](int buf) {
#pragma unroll
        for (int q = 0; q < 2; q++) {
            int idx = tid + q * 512;
            int row = idx >> 4, f = idx & 15;
            __nv_bfloat162 a0 = __float22bfloat162_rn(make_float2(pa[q].x, pa[q].y));
            __nv_bfloat162 a1 = __float22bfloat162_rn(make_float2(pa[q].z, pa[q].w));
            __nv_bfloat162 b0 = __float22bfloat162_rn(make_float2(pb[q].x, pb[q].y));
            __nv_bfloat162 b1 = __float22bfloat162_rn(make_float2(pb[q].z, pb[q].w));
            uint2 va, vb;
            va.x = reinterpret_cast<uint32_t&>(a0); va.y = reinterpret_cast<uint32_t&>(a1);
            vb.x = reinterpret_cast<uint32_t&>(b0); vb.y = reinterpret_cast<uint32_t&>(b1);
            *reinterpret_cast<uint2*>(Asm + (size_t)buf * 4608 + row * 72 + f * 4) = va;
            *reinterpret_cast<uint2*>(Bsm + (size_t)buf * 4608 + row * 72 + f * 4) = vb;
        }
    };

    wmma::fragment<wmma::accumulator, 16, 16, 16, float> c0;
    wmma::fill_fragment(c0, 0.0f);

    LDG(0);
    STS(0);
    __syncthreads();

#pragma unroll 1
    for (int s = 0; s < 8; s++) {
        const int buf = s & 1;
        if (s + 1 < 8) LDG(s + 1);
#pragma unroll
        for (int ks = 0; ks < 4; ks++) {
            wmma::fragment<wmma::matrix_a, 16, 16, 16, __nv_bfloat16, wmma::row_major> a;
            wmma::fragment<wmma::matrix_b, 16, 16, 16, __nv_bfloat16, wmma::col_major> b0;
            wmma::load_matrix_sync(a,  Asm + (size_t)buf * 4608 + (wr * 16) * 72 + ks * 16, 72);
            wmma::load_matrix_sync(b0, Bsm + (size_t)buf * 4608 + (wc * 16) * 72 + ks * 16, 72);
            wmma::mma_sync(c0, a, b0, c0);
        }
        if (s + 1 < 8) STS(buf ^ 1);
        __syncthreads();
    }

    // ---- epilogue: stage fp32, +bias, round bf16, store g_Hb, SS partials
    float* stage = reinterpret_cast<float*>(dynb);   // [64][68]
    wmma::store_matrix_sync(stage + (size_t)(wr * 16) * 68 + wc * 16, c0, 68, wmma::mem_row_major);
    __syncthreads();
#pragma unroll
    for (int t = 0; t < 2; t++) {
        int f4 = tid + t * 512;
        int row = f4 >> 4, c4 = (f4 & 15) * 4;
        float4 v = *reinterpret_cast<const float4*>(stage + (size_t)row * 68 + c4);
        float4 bv = *reinterpret_cast<const float4*>(bias + n0 + c4);
        __nv_bfloat162 lo = __float22bfloat162_rn(make_float2(v.x + bv.x, v.y + bv.y));
        __nv_bfloat162 hi = __float22bfloat162_rn(make_float2(v.z + bv.z, v.w + bv.w));
        *reinterpret_cast<__nv_bfloat162*>(g_Hb + (size_t)(m0 + row) * FOUT + n0 + c4)     = lo;
        *reinterpret_cast<__nv_bfloat162*>(g_Hb + (size_t)(m0 + row) * FOUT + n0 + c4 + 2) = hi;
        float lx = __bfloat162float(lo.x), ly = __bfloat162float(lo.y);
        float hx = __bfloat162float(hi.x), hy = __bfloat162float(hi.y);
        *reinterpret_cast<float4*>(stage + (size_t)row * 68 + c4) = make_float4(lx, ly, hx, hy);
    }
    __syncthreads();
    {
        int row = tid >> 3;                   // 64 rows x 8 threads x 8 cols
        int cg = (tid & 7) * 8;
        float ss = 0.0f;
#pragma unroll
        for (int i = 0; i < 2; i++) {
            float4 v = *reinterpret_cast<const float4*>(stage + (size_t)row * 68 + cg + i * 4);
            ss += v.x * v.x + v.y * v.y + v.z * v.z + v.w * v.w;
        }
        ss += __shfl_xor_sync(0xffffffffu, ss, 1);
        ss += __shfl_xor_sync(0xffffffffu, ss, 2);
        ss += __shfl_xor_sync(0xffffffffu, ss, 4);
        if ((tid & 7) == 0) g_ss2[nb][m0 + row] = ss;
    }
}

// ================= K2: fused Gram (bf16) + softmax + KL ======================
// 64 CTAs x 512 thr (16 warps). CTA = (batch b, 16-row tile). Warp w owns
// output cols w*16..+15. A (16x512, stride 520) resident; B streamed k=64.
__global__ __launch_bounds__(512, 1)
void k2_gram_kl(float* __restrict__ out) {
    extern __shared__ __align__(16) float dynf[];
    __nv_bfloat16* Asm = reinterpret_cast<__nv_bfloat16*>(dynf);            // [16][520]
    __nv_bfloat16* Bsm = reinterpret_cast<__nv_bfloat16*>(dynf) + 16 * 520; // [2][256][72]
    __shared__ float inv_s[PP];
    __shared__ unsigned long long sh1[PP];
    __shared__ unsigned long long sh2[PP];
    __shared__ double wsum[16];

    const int cta = blockIdx.x;
    const int b = cta >> 4;
    const int m0 = (cta & 15) * 16;
    const int tid = threadIdx.x;
    const int wid = tid >> 5, lane = tid & 31;
    const __nv_bfloat16* Hb = g_Hb + (size_t)b * PP * FOUT;

    // ---- A tile: 16 x 512 bf16 = 1024 x 16B, 2 per thread
    float4 pa4[2];
#pragma unroll
    for (int q = 0; q < 2; q++) {
        int idx = tid + q * 512;
        int row = idx >> 6, f = idx & 63;
        pa4[q] = *reinterpret_cast<const float4*>(
            reinterpret_cast<const char*>(Hb + (size_t)(m0 + row) * FOUT) + f * 16);
    }
    // ---- B chunk staging: 256 rows x 64 bf16 = 2048 x 16B, 4 per thread
    float4 pb4[4];
    auto LDG_B = [&](int s) {
#pragma unroll
        for (int q = 0; q < 4; q++) {
            int idx = tid + q * 512;
            int row = idx >> 3, f = idx & 7;
            pb4[q] = *reinterpret_cast<const float4*>(
                reinterpret_cast<const char*>(Hb + (size_t)row * FOUT) + s * 128 + f * 16);
        }
    };
    auto STS_B = [&](int buf) {
#pragma unroll
        for (int q = 0; q < 4; q++) {
            int idx = tid + q * 512;
            int row = idx >> 3, f = idx & 7;
            *reinterpret_cast<float4*>(
                reinterpret_cast<char*>(Bsm + (size_t)buf * 256 * 72) + row * 144 + f * 16) = pb4[q];
        }
    };

    LDG_B(0);
#pragma unroll
    for (int q = 0; q < 2; q++) {
        int idx = tid + q * 512;
        int row = idx >> 6, f = idx & 63;
        *reinterpret_cast<float4*>(reinterpret_cast<char*>(Asm) + row * 1040 + f * 16) = pa4[q];
    }
    // metadata (overlaps loads)
    if (tid < 256) {
        int q = tid;
        float ss = 0.0f;
#pragma unroll
        for (int nb = 0; nb < 8; nb++) ss += g_ss2[nb][b * PP + q];
        inv_s[q] = 1.0f / fmaxf(sqrtf(ss), 1e-12f);
        sh1[q] = g_h1[b * PP + q];
        sh2[q] = g_h2[b * PP + q];
    }
    STS_B(0);
    __syncthreads();

    wmma::fragment<wmma::accumulator, 16, 16, 16, float> c0;
    wmma::fill_fragment(c0, 0.0f);

#pragma unroll 1
    for (int s = 0; s < 8; s++) {
        const int buf = s & 1;
        if (s + 1 < 8) LDG_B(s + 1);
#pragma unroll
        for (int ks = 0; ks < 4; ks++) {
            wmma::fragment<wmma::matrix_a, 16, 16, 16, __nv_bfloat16, wmma::row_major> a;
            wmma::fragment<wmma::matrix_b, 16, 16, 16, __nv_bfloat16, wmma::col_major> b0;
            wmma::load_matrix_sync(a, Asm + s * 64 + ks * 16, 520);
            wmma::load_matrix_sync(b0, Bsm + (size_t)buf * 256 * 72 + (size_t)(wid * 16) * 72 + ks * 16, 72);
            wmma::mma_sync(c0, a, b0, c0);
        }
        if (s + 1 < 8) STS_B(buf ^ 1);
        __syncthreads();
    }

    // ---- stage S tile [16][260] fp32
    float* stageS = dynf;
    wmma::store_matrix_sync(stageS + wid * 16, c0, 260, wmma::mem_row_major);
    __syncthreads();

    // ---- softmax + KL: 16 warps x 1 row
    const float INV_TAU = 1.0f / 0.07f;
    {
        const int pl = wid;
        const float* Sr = stageS + (size_t)pl * 260;
        const float ip = inv_s[m0 + pl] * INV_TAU;
        float s[8];
        float mx = -1e30f;
#pragma unroll
        for (int j = 0; j < 8; j++) {
            int q = lane + 32 * j;
            s[j] = Sr[q] * ip * inv_s[q];
            mx = fmaxf(mx, s[j]);
        }
#pragma unroll
        for (int o = 16; o > 0; o >>= 1) mx = fmaxf(mx, __shfl_xor_sync(0xffffffffu, mx, o));
        float z = 0.0f;
#pragma unroll
        for (int j = 0; j < 8; j++) z += __expf(s[j] - mx);
#pragma unroll
        for (int o = 16; o > 0; o >>= 1) z += __shfl_xor_sync(0xffffffffu, z, o);
        float lse = mx + logf(z);

        unsigned long long h1p = sh1[m0 + pl], h2p = sh2[m0 + pl];
        int cnt = 0;
        bool match[8];
#pragma unroll
        for (int j = 0; j < 8; j++) {
            int q = lane + 32 * j;
            match[j] = (sh1[q] == h1p) && (sh2[q] == h2p);
            cnt += match[j] ? 1 : 0;
        }
#pragma unroll
        for (int o = 16; o > 0; o >>= 1) cnt += __shfl_xor_sync(0xffffffffu, cnt, o);

        float logn = logf((float)cnt);
        float contrib = 0.0f;
#pragma unroll
        for (int j = 0; j < 8; j++) {
            if (match[j]) {
                float lp = s[j] - lse;
                lp = fminf(fmaxf(lp, -11.512925464970229f),      // log(1e-5)
                           -1.0000050000290891e-05f);            // log(1-1e-5)
                contrib += (-logn - lp);
            }
        }
#pragma unroll
        for (int o = 16; o > 0; o >>= 1) contrib += __shfl_xor_sync(0xffffffffu, contrib, o);
        if (lane == 0) wsum[wid] = (double)contrib / (double)cnt;
    }
    __syncthreads();
    if (tid == 0) {
        double blk = 0.0;
#pragma unroll
        for (int i = 0; i < 16; i++) blk += wsum[i];
        atomicAdd(&g_loss, blk);
        __threadfence();
        if (atomicAdd(&g_done, 1u) == 63u) {     // last finisher writes output
            *(volatile unsigned int*)&g_done = 0;
            double l = atomicAdd(&g_loss, 0.0);
            out[0] = (float)(l * (1.0 / (double)(BB * PP)));
        }
    }
}

// ================= launch ====================================================
extern "C" void kernel_launch(void* const* d_in, const int* in_sizes, int n_in,
                              void* d_out, int out_size) {
    const float* inputs = (const float*)d_in[0];
    const float* labels = (const float*)d_in[1];
    const float* W      = (const float*)d_in[2];
    const float* bias   = (const float*)d_in[3];
    float* out = (float*)d_out;

    const int K1_SMEM = 2 * 2 * 64 * 72 * 2;                 // 36864 B
    const int K2_SMEM = (16 * 520 + 2 * 256 * 72) * 2;       // 90368 B
    cudaFuncSetAttribute(k1_gemm,    cudaFuncAttributeMaxDynamicSharedMemorySize, K1_SMEM);
    cudaFuncSetAttribute(k2_gram_kl, cudaFuncAttributeMaxDynamicSharedMemorySize, K2_SMEM);

    k1_gemm<<<128, 512, K1_SMEM>>>(inputs, labels, W, bias);
    k2_gram_kl<<<64, 512, K2_SMEM>>>(out);
}